// round 15
// baseline (speedup 1.0000x reference)
#include <cuda_runtime.h>
#include <cuda_bf16.h>
#include <cstdint>

// Problem constants
#define NN 10000
#define DD 256
#define HH 512
#define EE 320000

// Scratch (device globals: allocation-free rule; ~30MB proven-safe footprint)
__device__ float4 g_agg[NN * (DD / 4)];   // [N, 256]  aggregated messages
__device__ float4 g_h  [NN * (HH / 4)];   // [N, 512]  relu(cat @ W_conv + b)

// ---------------------------------------------------------------------------
__global__ void k_zero_agg() {
    int i = blockIdx.x * blockDim.x + threadIdx.x;
    if (i < NN * (DD / 4)) g_agg[i] = make_float4(0.f, 0.f, 0.f, 0.f);
}

__global__ void k_init_out(float* __restrict__ out, const float* __restrict__ b2) {
    int i = blockIdx.x * blockDim.x + threadIdx.x;
    if (i < NN) out[i] = b2[0];
}

// SpMM scatter: agg[dst] += x[src] * val   (one warp per edge, float4 atomics)
__global__ void k_scatter(const float4* __restrict__ x4,
                          const int*    __restrict__ esrc,
                          const int*    __restrict__ edst,
                          const float*  __restrict__ eval) {
    int gid  = blockIdx.x * blockDim.x + threadIdx.x;
    int w    = gid >> 5;
    int lane = gid & 31;
    if (w >= EE) return;
    int   s = __ldg(esrc + w);
    int   d = __ldg(edst + w);
    float v = __ldg(eval + w);
    const float4* xr = x4    + (size_t)s * (DD / 4);
    float4*       ar = g_agg + (size_t)d * (DD / 4);
    #pragma unroll
    for (int j = 0; j < 2; j++) {
        int c = lane + j * 32;
        float4 t = __ldg(xr + c);
        t.x *= v; t.y *= v; t.z *= v; t.w *= v;
        atomicAdd(ar + c, t);
    }
}

// ---------------------------------------------------------------------------
// SIMT fp32 GEMM, occupancy-oriented: BM=128, BN=64, BK=16, 256 threads,
// 8 rows x 4 cols per thread (packed f32x2 accumulators, 32 acc regs).
// ~65-70 regs -> 3-4 CTAs/SM (24-32 warps) for latency hiding, with
// LDS-instr/FMA ratio 0.094 (below R1's L1-bound 0.125).
#define BM 128
#define BN 64
#define BK 16

#define SPLAT64(dst, s)  asm("mov.b64 %0, {%1, %1};" : "=l"(dst) : "f"(s))
#define FMA2(acc, ap, bp) \
    asm("fma.rn.f32x2 %0, %1, %2, %0;" : "+l"(acc) : "l"(ap), "l"(bp))
#define UNPACK64(lo, hi, p) \
    asm("mov.b64 {%0, %1}, %2;" : "=f"(lo), "=f"(hi) : "l"(p))

// GEMM1: h = relu( [x | agg] @ W_conv + b_conv )    A:[N,512] B:[512,512]
__global__ __launch_bounds__(256)
void k_gemm1(const float* __restrict__ x,
             const float* __restrict__ Wc,
             const float* __restrict__ bc) {
    __shared__ float As[BK][BM];
    __shared__ float Bs[BK][BN];

    const int tid = threadIdx.x;
    const int tx = tid & 15;          // 16 col-threads * 4 cols = 64
    const int ty = tid >> 4;          // 16 row-threads * 8 rows = 128
    const int rowBase = blockIdx.y * BM;
    const int colBase = blockIdx.x * BN;

    // A load: 128 rows x 16 cols = 512 float4 -> 2 per thread
    const int la_row = tid >> 2;      // 0..63 (+64 second half)
    const int la_kc  = (tid & 3) * 4; // 0,4,8,12
    // B load: 16 rows x 64 cols = 256 float4 -> 1 per thread
    const int lb_k   = tid >> 4;      // 0..15
    const int lb_nc  = (tid & 15) * 4;

    const float* aggf = (const float*)g_agg;

    unsigned long long acc[8][2];
    #pragma unroll
    for (int i = 0; i < 8; i++) { acc[i][0] = 0ull; acc[i][1] = 0ull; }

    for (int kt = 0; kt < 2 * DD; kt += BK) {
        const float* Asrc = (kt < DD) ? x : aggf;
        const int kk0 = kt & (DD - 1);
        #pragma unroll
        for (int half = 0; half < 2; half++) {
            int gr = rowBase + la_row + half * 64;
            float4 a4 = make_float4(0.f, 0.f, 0.f, 0.f);
            if (gr < NN)
                a4 = *(const float4*)(Asrc + (size_t)gr * DD + kk0 + la_kc);
            As[la_kc + 0][la_row + half * 64] = a4.x;
            As[la_kc + 1][la_row + half * 64] = a4.y;
            As[la_kc + 2][la_row + half * 64] = a4.z;
            As[la_kc + 3][la_row + half * 64] = a4.w;
        }
        {
            float4 b4 = *(const float4*)(Wc + (size_t)(kt + lb_k) * HH + colBase + lb_nc);
            *(float4*)&Bs[lb_k][lb_nc] = b4;
        }
        __syncthreads();

        #pragma unroll
        for (int kk = 0; kk < BK; kk++) {
            float4 a0 = *(const float4*)&As[kk][ty * 4];
            float4 a1 = *(const float4*)&As[kk][64 + ty * 4];
            ulonglong2 bp = *(const ulonglong2*)&Bs[kk][tx * 4];  // pairs (b0,b1),(b2,b3)
            float av[8] = {a0.x, a0.y, a0.z, a0.w, a1.x, a1.y, a1.z, a1.w};
            #pragma unroll
            for (int i = 0; i < 8; i++) {
                unsigned long long ap;
                SPLAT64(ap, av[i]);
                FMA2(acc[i][0], ap, bp.x);
                FMA2(acc[i][1], ap, bp.y);
            }
        }
        __syncthreads();
    }

    // epilogue: + bias, relu, store h (one float4 per row-slot)
    float* hf = (float*)g_h;
    const float4 bias0 = *(const float4*)(bc + colBase + tx * 4);
    #pragma unroll
    for (int i = 0; i < 8; i++) {
        int r = rowBase + (i < 4 ? ty * 4 + i : 64 + ty * 4 + (i - 4));
        if (r < NN) {
            float c0, c1, c2, c3;
            UNPACK64(c0, c1, acc[i][0]);
            UNPACK64(c2, c3, acc[i][1]);
            float4 o;
            o.x = fmaxf(c0 + bias0.x, 0.f);
            o.y = fmaxf(c1 + bias0.y, 0.f);
            o.z = fmaxf(c2 + bias0.z, 0.f);
            o.w = fmaxf(c3 + bias0.w, 0.f);
            *(float4*)(hf + (size_t)r * HH + colBase + tx * 4) = o;
        }
    }
}

// GEMM2 (fused head): z = prelu(h @ W1 + b1); out[r] += sum_c z[r,c]*W2[c]
__global__ __launch_bounds__(256)
void k_gemm2(const float* __restrict__ W1,
             const float* __restrict__ b1,
             const float* __restrict__ pa,
             const float* __restrict__ W2,
             float* __restrict__ out) {
    __shared__ float As[BK][BM];
    __shared__ float Bs[BK][BN];

    const int tid = threadIdx.x;
    const int tx = tid & 15;
    const int ty = tid >> 4;
    const int rowBase = blockIdx.y * BM;
    const int colBase = blockIdx.x * BN;

    const int la_row = tid >> 2;
    const int la_kc  = (tid & 3) * 4;
    const int lb_k   = tid >> 4;
    const int lb_nc  = (tid & 15) * 4;

    const float* hf = (const float*)g_h;

    unsigned long long acc[8][2];
    #pragma unroll
    for (int i = 0; i < 8; i++) { acc[i][0] = 0ull; acc[i][1] = 0ull; }

    for (int kt = 0; kt < HH; kt += BK) {
        #pragma unroll
        for (int half = 0; half < 2; half++) {
            int gr = rowBase + la_row + half * 64;
            float4 a4 = make_float4(0.f, 0.f, 0.f, 0.f);
            if (gr < NN)
                a4 = *(const float4*)(hf + (size_t)gr * HH + kt + la_kc);
            As[la_kc + 0][la_row + half * 64] = a4.x;
            As[la_kc + 1][la_row + half * 64] = a4.y;
            As[la_kc + 2][la_row + half * 64] = a4.z;
            As[la_kc + 3][la_row + half * 64] = a4.w;
        }
        {
            float4 b4 = *(const float4*)(W1 + (size_t)(kt + lb_k) * HH + colBase + lb_nc);
            *(float4*)&Bs[lb_k][lb_nc] = b4;
        }
        __syncthreads();

        #pragma unroll
        for (int kk = 0; kk < BK; kk++) {
            float4 a0 = *(const float4*)&As[kk][ty * 4];
            float4 a1 = *(const float4*)&As[kk][64 + ty * 4];
            ulonglong2 bp = *(const ulonglong2*)&Bs[kk][tx * 4];
            float av[8] = {a0.x, a0.y, a0.z, a0.w, a1.x, a1.y, a1.z, a1.w};
            #pragma unroll
            for (int i = 0; i < 8; i++) {
                unsigned long long ap;
                SPLAT64(ap, av[i]);
                FMA2(acc[i][0], ap, bp.x);
                FMA2(acc[i][1], ap, bp.y);
            }
        }
        __syncthreads();
    }

    // epilogue: bias, PReLU, dot with W2, reduce across 16 col-threads, atomic
    const float4 b1v = *(const float4*)(b1 + colBase + tx * 4);
    const float4 pav = *(const float4*)(pa + colBase + tx * 4);
    const float4 w2v = *(const float4*)(W2 + colBase + tx * 4);

    #pragma unroll
    for (int i = 0; i < 8; i++) {
        float c0, c1, c2, c3;
        UNPACK64(c0, c1, acc[i][0]);
        UNPACK64(c2, c3, acc[i][1]);
        float z0 = c0 + b1v.x; z0 = z0 > 0.f ? z0 : pav.x * z0;
        float z1 = c1 + b1v.y; z1 = z1 > 0.f ? z1 : pav.y * z1;
        float z2 = c2 + b1v.z; z2 = z2 > 0.f ? z2 : pav.z * z2;
        float z3 = c3 + b1v.w; z3 = z3 > 0.f ? z3 : pav.w * z3;
        float s = fmaf(z0, w2v.x, fmaf(z1, w2v.y, fmaf(z2, w2v.z, z3 * w2v.w)));
        // reduce across tx (16-lane groups aligned within the warp)
        #pragma unroll
        for (int m = 8; m > 0; m >>= 1)
            s += __shfl_xor_sync(0xffffffffu, s, m);
        if (tx == 0) {
            int r = rowBase + (i < 4 ? ty * 4 + i : 64 + ty * 4 + (i - 4));
            if (r < NN) atomicAdd(out + r, s);
        }
    }
}

// ---------------------------------------------------------------------------
extern "C" void kernel_launch(void* const* d_in, const int* in_sizes, int n_in,
                              void* d_out, int out_size) {
    const float* x     = (const float*)d_in[0];
    const int*   esrc  = (const int*)  d_in[1];
    const int*   edst  = (const int*)  d_in[2];
    const float* eval  = (const float*)d_in[3];
    const float* Wc    = (const float*)d_in[4];
    const float* bc    = (const float*)d_in[5];
    const float* W1    = (const float*)d_in[6];
    const float* b1    = (const float*)d_in[7];
    const float* pa    = (const float*)d_in[8];
    const float* W2    = (const float*)d_in[9];
    const float* b2    = (const float*)d_in[10];
    float* out = (float*)d_out;

    // 1) zero agg + seed out with b2
    k_zero_agg<<<(NN * (DD / 4) + 255) / 256, 256>>>();
    k_init_out<<<(NN + 255) / 256, 256>>>(out, b2);

    // 2) SpMM scatter (warp per edge)
    {
        long threads = (long)EE * 32;
        int blocks = (int)((threads + 255) / 256);
        k_scatter<<<blocks, 256>>>((const float4*)x, esrc, edst, eval);
    }

    // 3) GEMM1: h = relu([x|agg] @ W_conv + b_conv)
    {
        dim3 grid(HH / BN, (NN + BM - 1) / BM);
        k_gemm1<<<grid, 256>>>(x, Wc, bc);
    }

    // 4) GEMM2 fused with PReLU + W2 matvec head
    {
        dim3 grid(HH / BN, (NN + BM - 1) / BM);
        k_gemm2<<<grid, 256>>>(W1, b1, pa, W2, out);
    }
}